// round 15
// baseline (speedup 1.0000x reference)
#include <cuda_runtime.h>
#include <cuda_fp16.h>

#define NN 100000
#define EE 800000
#define DD 64

#define SCATTER_BLOCKS 3125   // ceil(EE/256)
#define GEMM_BLOCKS    1563   // ceil(NN/64)

// Scratch (allocation-free rule: __device__ globals)
// g stored fp16: row = 32 x uint32 (half2) = 128 bytes.
// ONE EXTRA ROW (index NN), never written -> permanent zeros (pad target).
__device__ unsigned g_h[(NN + 1) * 32];
__device__ float g_x[NN * DD];      // ping-pong x between rounds (fp32)
__device__ int   g_deg[NN];
__device__ int   g_rowptr[NN + 1];
__device__ int   g_cursor[NN];
__device__ int   g_col[EE];
__device__ float g_dis[NN];

// ---------------- CSR build ----------------

__global__ void k_hist(const int* __restrict__ dst, int e) {
    int i = blockIdx.x * blockDim.x + threadIdx.x;
    if (i < e) atomicAdd(&g_deg[dst[i]], 1);
}

// Single-block coalesced scan (R12-proven); dis = rsqrt(deg+1); re-zeroes deg.
__global__ __launch_bounds__(1024) void k_scan(int n) {
    __shared__ int s_tot[32];
    __shared__ int s_base[32];

    int t    = threadIdx.x;
    int w    = t >> 5;
    int lane = t & 31;
    int chunk = (n + 31) / 32 / 32 * 32;
    if (chunk * 32 < n) chunk += 32;
    int lo = w * chunk;
    int hi = min(lo + chunk, n);

    int s = 0;
    for (int i = lo + lane; i < hi; i += 32) s += g_deg[i];
    #pragma unroll
    for (int o = 16; o > 0; o >>= 1) s += __shfl_xor_sync(0xffffffffu, s, o);
    if (lane == 0) s_tot[w] = s;
    __syncthreads();

    if (w == 0) {
        int v = s_tot[lane];
        int x = v;
        #pragma unroll
        for (int o = 1; o < 32; o <<= 1) {
            int y = __shfl_up_sync(0xffffffffu, x, o);
            if (lane >= o) x += y;
        }
        s_base[lane] = x - v;
    }
    __syncthreads();

    int run = s_base[w];
    for (int start = lo; start < hi; start += 32) {
        int i = start + lane;
        bool valid = (i < hi);
        int v = valid ? g_deg[i] : 0;
        int x = v;
        #pragma unroll
        for (int o = 1; o < 32; o <<= 1) {
            int y = __shfl_up_sync(0xffffffffu, x, o);
            if (lane >= o) x += y;
        }
        int excl = run + x - v;
        if (valid) {
            g_rowptr[i] = excl;
            g_cursor[i] = excl;
            g_dis[i]    = rsqrtf((float)(v + 1));
            g_deg[i]    = 0;
        }
        run += __shfl_sync(0xffffffffu, x, 31);
    }
    if (hi == n && lane == 31) g_rowptr[n] = run;
}

// ---------------- GEMM core: writes fp16-packed g (R13-proven) ----------------

__device__ __forceinline__ void gemm_tile(const float* __restrict__ x,
                                          const float* __restrict__ W,
                                          int rowbase, int n,
                                          float* Wsh, float* Xsh, int t) {
    {
        const float4* W4 = (const float4*)W;
        float4* Ws4 = (float4*)Wsh;
        #pragma unroll
        for (int i = t; i < 1024; i += 256) Ws4[i] = W4[i];
    }
    {
        float4* Xs4 = (float4*)Xsh;
        #pragma unroll
        for (int i = t; i < 1024; i += 256) {
            int r = i >> 4, k4 = i & 15;
            float4 v = make_float4(0.f, 0.f, 0.f, 0.f);
            if (rowbase + r < n)
                v = ((const float4*)(x + (size_t)(rowbase + r) * DD))[k4];
            Xs4[i] = v;
        }
    }
    __syncthreads();

    int tx = t & 15;
    int ty = t >> 4;

    float acc[4][4];
    #pragma unroll
    for (int i = 0; i < 4; i++)
        #pragma unroll
        for (int j = 0; j < 4; j++) acc[i][j] = 0.f;

    #pragma unroll 8
    for (int k = 0; k < 64; k++) {
        float4 w = ((const float4*)(Wsh + k * DD))[tx];
        float a0 = Xsh[(ty * 4 + 0) * DD + k];
        float a1 = Xsh[(ty * 4 + 1) * DD + k];
        float a2 = Xsh[(ty * 4 + 2) * DD + k];
        float a3 = Xsh[(ty * 4 + 3) * DD + k];
        acc[0][0] += a0 * w.x; acc[0][1] += a0 * w.y; acc[0][2] += a0 * w.z; acc[0][3] += a0 * w.w;
        acc[1][0] += a1 * w.x; acc[1][1] += a1 * w.y; acc[1][2] += a1 * w.z; acc[1][3] += a1 * w.w;
        acc[2][0] += a2 * w.x; acc[2][1] += a2 * w.y; acc[2][2] += a2 * w.z; acc[2][3] += a2 * w.w;
        acc[3][0] += a3 * w.x; acc[3][1] += a3 * w.y; acc[3][2] += a3 * w.z; acc[3][3] += a3 * w.w;
    }

    #pragma unroll
    for (int i = 0; i < 4; i++) {
        int r = rowbase + ty * 4 + i;
        if (r < n) {
            float d = g_dis[r];
            __half2 p0 = __floats2half2_rn(acc[i][0] * d, acc[i][1] * d);
            __half2 p1 = __floats2half2_rn(acc[i][2] * d, acc[i][3] * d);
            uint2 o;
            o.x = *reinterpret_cast<unsigned*>(&p0);
            o.y = *reinterpret_cast<unsigned*>(&p1);
            ((uint2*)(g_h + (size_t)r * 32))[tx] = o;
        }
    }
}

// Fused: blocks [0, SCATTER_BLOCKS) do CSR scatter; the rest do round-0 GEMM.
__global__ __launch_bounds__(256) void k_scatter_gemm(const int* __restrict__ src,
                                                      const int* __restrict__ dst, int e,
                                                      const float* __restrict__ x,
                                                      const float* __restrict__ W, int n) {
    __shared__ float Wsh[DD * DD];
    __shared__ float Xsh[DD * DD];

    if (blockIdx.x < SCATTER_BLOCKS) {
        int i = blockIdx.x * 256 + threadIdx.x;
        if (i < e) {
            int d = dst[i];
            int pos = atomicAdd(&g_cursor[d], 1);
            g_col[pos] = src[i];
        }
        return;
    }
    int rowbase = (blockIdx.x - SCATTER_BLOCKS) * 64;
    gemm_tile(x, W, rowbase, n, Wsh, Xsh, threadIdx.x);
}

// Standalone GEMM for rounds 1..3
__global__ __launch_bounds__(256) void k_gemm(const float* __restrict__ x,
                                              const float* __restrict__ W, int n) {
    __shared__ float Wsh[DD * DD];
    __shared__ float Xsh[DD * DD];
    gemm_tile(x, W, blockIdx.x * 64, n, Wsh, Xsh, threadIdx.x);
}

// QUAD GATHER: warp per node; each LDG.128 fetches FOUR edge rows
// (8 lanes x 16B per 128B fp16 row). Edge stream = neighbors ++ [self];
// pad slots -> permanent zero row NN. Fully converged control flow.
__global__ __launch_bounds__(256) void k_agg_ln(const float* __restrict__ b,
                                                const float* __restrict__ gamma,
                                                const float* __restrict__ beta,
                                                float* __restrict__ out, int n) {
    int v    = (blockIdx.x * blockDim.x + threadIdx.x) >> 5;
    int lane = threadIdx.x & 31;
    if (v >= n) return;

    int grp = lane >> 3;      // which edge of a quad (0..3)
    int l8  = lane & 7;       // 16B feature chunk within row (features 8*l8..8*l8+7)

    float dv  = g_dis[v];
    int rp0   = g_rowptr[v];
    int rp1   = g_rowptr[v + 1];
    int deg   = rp1 - rp0;
    int cnt   = deg + 1;      // + self-loop

    // accumulators: 8 features as 4 float2
    float2 A0 = make_float2(0.f, 0.f), A1 = A0, A2 = A0, A3 = A0;

    const uint4* gh4 = (const uint4*)g_h;   // row u = gh4[u*8 + l8]

    for (int base = 0; base < cnt; base += 32) {
        int j = base + lane;                 // edge ordinal
        int c;
        if (j < deg)        c = g_col[rp0 + j];
        else if (j == deg)  c = v;           // self-loop
        else                c = NN;          // zero pad
        int quads = (min(32, cnt - base) + 3) >> 2;   // warp-uniform 1..8
        for (int q = 0; q < quads; q++) {
            int u = __shfl_sync(0xffffffffu, c, q * 4 + grp);
            uint4 m = gh4[(size_t)u * 8 + l8];
            __half2 h0 = *reinterpret_cast<__half2*>(&m.x);
            __half2 h1 = *reinterpret_cast<__half2*>(&m.y);
            __half2 h2 = *reinterpret_cast<__half2*>(&m.z);
            __half2 h3 = *reinterpret_cast<__half2*>(&m.w);
            float2 f0 = __half22float2(h0);
            float2 f1 = __half22float2(h1);
            float2 f2 = __half22float2(h2);
            float2 f3 = __half22float2(h3);
            A0.x += f0.x; A0.y += f0.y;
            A1.x += f1.x; A1.y += f1.y;
            A2.x += f2.x; A2.y += f2.y;
            A3.x += f3.x; A3.y += f3.y;
        }
    }

    // Combine the 4 lane-groups (same l8, different grp hold partial sums)
    #pragma unroll
    for (int o = 8; o <= 16; o <<= 1) {
        A0.x += __shfl_xor_sync(0xffffffffu, A0.x, o);
        A0.y += __shfl_xor_sync(0xffffffffu, A0.y, o);
        A1.x += __shfl_xor_sync(0xffffffffu, A1.x, o);
        A1.y += __shfl_xor_sync(0xffffffffu, A1.y, o);
        A2.x += __shfl_xor_sync(0xffffffffu, A2.x, o);
        A2.y += __shfl_xor_sync(0xffffffffu, A2.y, o);
        A3.x += __shfl_xor_sync(0xffffffffu, A3.x, o);
        A3.y += __shfl_xor_sync(0xffffffffu, A3.y, o);
    }

    // bias + dv
    const float4* b4 = (const float4*)b;
    float4 bb0 = b4[2 * l8 + 0];
    float4 bb1 = b4[2 * l8 + 1];
    float a0 = A0.x * dv + bb0.x;
    float a1 = A0.y * dv + bb0.y;
    float a2 = A1.x * dv + bb0.z;
    float a3 = A1.y * dv + bb0.w;
    float a4 = A2.x * dv + bb1.x;
    float a5 = A2.y * dv + bb1.y;
    float a6 = A3.x * dv + bb1.z;
    float a7 = A3.y * dv + bb1.w;

    // LayerNorm: 8 features/lane, reduce across the 8 l8-chunks (xor 1,2,4
    // stays within the 8-lane group; all groups hold identical data)
    float s  = ((a0 + a1) + (a2 + a3)) + ((a4 + a5) + (a6 + a7));
    float ss = ((a0 * a0 + a1 * a1) + (a2 * a2 + a3 * a3))
             + ((a4 * a4 + a5 * a5) + (a6 * a6 + a7 * a7));
    #pragma unroll
    for (int o = 1; o <= 4; o <<= 1) {
        s  += __shfl_xor_sync(0xffffffffu, s, o);
        ss += __shfl_xor_sync(0xffffffffu, ss, o);
    }
    float mu  = s * (1.f / 64.f);
    float var = ss * (1.f / 64.f) - mu * mu;
    float inv = rsqrtf(var + 1e-5f);

    const float4* gm4 = (const float4*)gamma;
    const float4* bt4 = (const float4*)beta;
    float4 gm0 = gm4[2 * l8 + 0], gm1 = gm4[2 * l8 + 1];
    float4 bt0 = bt4[2 * l8 + 0], bt1 = bt4[2 * l8 + 1];

    if (grp == 0) {                 // lanes 0..7 write the full row
        float4 o0, o1;
        o0.x = (a0 - mu) * inv * gm0.x + bt0.x;
        o0.y = (a1 - mu) * inv * gm0.y + bt0.y;
        o0.z = (a2 - mu) * inv * gm0.z + bt0.z;
        o0.w = (a3 - mu) * inv * gm0.w + bt0.w;
        o1.x = (a4 - mu) * inv * gm1.x + bt1.x;
        o1.y = (a5 - mu) * inv * gm1.y + bt1.y;
        o1.z = (a6 - mu) * inv * gm1.z + bt1.z;
        o1.w = (a7 - mu) * inv * gm1.w + bt1.w;
        float4* orow = (float4*)(out + (size_t)v * DD);
        orow[2 * l8 + 0] = o0;
        orow[2 * l8 + 1] = o1;
    }
}

// ---------------- launch ----------------

extern "C" void kernel_launch(void* const* d_in, const int* in_sizes, int n_in,
                              void* d_out, int out_size) {
    const float* x     = (const float*)d_in[0];
    const int*   ei    = (const int*)d_in[1];
    const float* W     = (const float*)d_in[2];
    const float* b     = (const float*)d_in[3];
    const float* gamma = (const float*)d_in[4];
    const float* beta  = (const float*)d_in[5];

    int n = in_sizes[0] / DD;      // 100000
    int e = in_sizes[1] / 2;       // 800000
    const int* src = ei;
    const int* dst = ei + e;

    k_hist<<<(e + 255) / 256, 256>>>(dst, e);                       // kernel 1
    k_scan<<<1, 1024>>>(n);                                         // kernel 2
    k_scatter_gemm<<<SCATTER_BLOCKS + GEMM_BLOCKS, 256>>>(          // kernel 3
        src, dst, e, x, W, n);

    int agg_blocks = (n + 7) / 8;   // warp per node, 8 warps/block

    const int NUM_ROUNDS = 4;
    for (int r = 0; r < NUM_ROUNDS; r++) {
        if (r > 0)
            k_gemm<<<GEMM_BLOCKS, 256>>>((const float*)g_x, W, n);
        float* xout = (r == NUM_ROUNDS - 1) ? (float*)d_out : g_x;
        k_agg_ln<<<agg_blocks, 256>>>(b, gamma, beta, xout, n);     // kernel 4 on r=0 -> PROFILED
    }
}

// round 16
// speedup vs baseline: 1.1601x; 1.1601x over previous
#include <cuda_runtime.h>
#include <cuda_fp16.h>
#include <cuda.h>

#define NN 100000
#define EE 800000
#define DD 64

#define SCATTER_BLOCKS 3125   // ceil(EE/256)
#define GEMM_BLOCKS    1563   // ceil(NN/64)

// Scratch (allocation-free rule: __device__ globals)
// g stored fp16: row = 32 x uint32 (half2) = 128 bytes.
__device__ unsigned g_h[NN * 32];
__device__ float g_x[NN * DD];      // ping-pong x between rounds (fp32)
__device__ int   g_deg[NN];
__device__ int   g_rowptr[NN + 1];
__device__ int   g_cursor[NN];
__device__ int   g_col[EE];
__device__ float g_dis[NN];

// ---------------- small PTX helpers ----------------

__device__ __forceinline__ unsigned smem_u32(const void* p) {
    unsigned r;
    asm("{ .reg .u64 t; cvta.to.shared.u64 t, %1; cvt.u32.u64 %0, t; }"
        : "=r"(r) : "l"(p));
    return r;
}

#define MBAR_INIT(a)      asm volatile("mbarrier.init.shared.b64 [%0], %1;" :: "r"(a), "r"(1u) : "memory")
#define MBAR_INVAL(a)     asm volatile("mbarrier.inval.shared.b64 [%0];" :: "r"(a) : "memory")
#define MBAR_EXPECT(a,tx) asm volatile("mbarrier.arrive.expect_tx.shared.b64 _, [%0], %1;" :: "r"(a), "r"(tx) : "memory")

#define MBAR_WAIT(a, ph) do {                                                  \
    unsigned _done;                                                            \
    asm volatile("{\n\t.reg .pred p;\n\t"                                      \
        "mbarrier.try_wait.parity.acquire.cta.shared::cta.b64 p, [%1], %2;\n\t"\
        "selp.b32 %0, 1, 0, p;\n\t}"                                           \
        : "=r"(_done) : "r"(a), "r"((unsigned)(ph)) : "memory");               \
    while (!_done) {                                                           \
        asm volatile("{\n\t.reg .pred p;\n\t"                                  \
            "mbarrier.try_wait.parity.acquire.cta.shared::cta.b64 p, [%1], %2, 0x989680;\n\t"\
            "selp.b32 %0, 1, 0, p;\n\t}"                                       \
            : "=r"(_done) : "r"(a), "r"((unsigned)(ph)) : "memory");           \
    }                                                                          \
} while (0)

#define TMA_ROW(smem, tmapp, row, mbar)                                        \
    asm volatile("cp.async.bulk.tensor.2d.shared::cta.global.tile.mbarrier::complete_tx::bytes " \
                 "[%0], [%1, {%2, %3}], [%4];"                                 \
                 :: "r"(smem), "l"(tmapp), "r"(0), "r"(row), "r"(mbar) : "memory")

// ---------------- CSR build ----------------

__global__ void k_hist(const int* __restrict__ dst, int e) {
    int i = blockIdx.x * blockDim.x + threadIdx.x;
    if (i < e) atomicAdd(&g_deg[dst[i]], 1);
}

// Single-block coalesced scan (R12-proven); dis = rsqrt(deg+1); re-zeroes deg.
__global__ __launch_bounds__(1024) void k_scan(int n) {
    __shared__ int s_tot[32];
    __shared__ int s_base[32];

    int t    = threadIdx.x;
    int w    = t >> 5;
    int lane = t & 31;
    int chunk = (n + 31) / 32 / 32 * 32;
    if (chunk * 32 < n) chunk += 32;
    int lo = w * chunk;
    int hi = min(lo + chunk, n);

    int s = 0;
    for (int i = lo + lane; i < hi; i += 32) s += g_deg[i];
    #pragma unroll
    for (int o = 16; o > 0; o >>= 1) s += __shfl_xor_sync(0xffffffffu, s, o);
    if (lane == 0) s_tot[w] = s;
    __syncthreads();

    if (w == 0) {
        int v = s_tot[lane];
        int x = v;
        #pragma unroll
        for (int o = 1; o < 32; o <<= 1) {
            int y = __shfl_up_sync(0xffffffffu, x, o);
            if (lane >= o) x += y;
        }
        s_base[lane] = x - v;
    }
    __syncthreads();

    int run = s_base[w];
    for (int start = lo; start < hi; start += 32) {
        int i = start + lane;
        bool valid = (i < hi);
        int v = valid ? g_deg[i] : 0;
        int x = v;
        #pragma unroll
        for (int o = 1; o < 32; o <<= 1) {
            int y = __shfl_up_sync(0xffffffffu, x, o);
            if (lane >= o) x += y;
        }
        int excl = run + x - v;
        if (valid) {
            g_rowptr[i] = excl;
            g_cursor[i] = excl;
            g_dis[i]    = rsqrtf((float)(v + 1));
            g_deg[i]    = 0;
        }
        run += __shfl_sync(0xffffffffu, x, 31);
    }
    if (hi == n && lane == 31) g_rowptr[n] = run;
}

// ---------------- GEMM core: writes fp16-packed g (R13-proven) ----------------

__device__ __forceinline__ void gemm_tile(const float* __restrict__ x,
                                          const float* __restrict__ W,
                                          int rowbase, int n,
                                          float* Wsh, float* Xsh, int t) {
    {
        const float4* W4 = (const float4*)W;
        float4* Ws4 = (float4*)Wsh;
        #pragma unroll
        for (int i = t; i < 1024; i += 256) Ws4[i] = W4[i];
    }
    {
        float4* Xs4 = (float4*)Xsh;
        #pragma unroll
        for (int i = t; i < 1024; i += 256) {
            int r = i >> 4, k4 = i & 15;
            float4 v = make_float4(0.f, 0.f, 0.f, 0.f);
            if (rowbase + r < n)
                v = ((const float4*)(x + (size_t)(rowbase + r) * DD))[k4];
            Xs4[i] = v;
        }
    }
    __syncthreads();

    int tx = t & 15;
    int ty = t >> 4;

    float acc[4][4];
    #pragma unroll
    for (int i = 0; i < 4; i++)
        #pragma unroll
        for (int j = 0; j < 4; j++) acc[i][j] = 0.f;

    #pragma unroll 8
    for (int k = 0; k < 64; k++) {
        float4 w = ((const float4*)(Wsh + k * DD))[tx];
        float a0 = Xsh[(ty * 4 + 0) * DD + k];
        float a1 = Xsh[(ty * 4 + 1) * DD + k];
        float a2 = Xsh[(ty * 4 + 2) * DD + k];
        float a3 = Xsh[(ty * 4 + 3) * DD + k];
        acc[0][0] += a0 * w.x; acc[0][1] += a0 * w.y; acc[0][2] += a0 * w.z; acc[0][3] += a0 * w.w;
        acc[1][0] += a1 * w.x; acc[1][1] += a1 * w.y; acc[1][2] += a1 * w.z; acc[1][3] += a1 * w.w;
        acc[2][0] += a2 * w.x; acc[2][1] += a2 * w.y; acc[2][2] += a2 * w.z; acc[2][3] += a2 * w.w;
        acc[3][0] += a3 * w.x; acc[3][1] += a3 * w.y; acc[3][2] += a3 * w.z; acc[3][3] += a3 * w.w;
    }

    #pragma unroll
    for (int i = 0; i < 4; i++) {
        int r = rowbase + ty * 4 + i;
        if (r < n) {
            float d = g_dis[r];
            __half2 p0 = __floats2half2_rn(acc[i][0] * d, acc[i][1] * d);
            __half2 p1 = __floats2half2_rn(acc[i][2] * d, acc[i][3] * d);
            uint2 o;
            o.x = *reinterpret_cast<unsigned*>(&p0);
            o.y = *reinterpret_cast<unsigned*>(&p1);
            ((uint2*)(g_h + (size_t)r * 32))[tx] = o;
        }
    }
}

// Fused: blocks [0, SCATTER_BLOCKS) do CSR scatter; the rest do round-0 GEMM.
__global__ __launch_bounds__(256) void k_scatter_gemm(const int* __restrict__ src,
                                                      const int* __restrict__ dst, int e,
                                                      const float* __restrict__ x,
                                                      const float* __restrict__ W, int n) {
    __shared__ float Wsh[DD * DD];
    __shared__ float Xsh[DD * DD];

    if (blockIdx.x < SCATTER_BLOCKS) {
        int i = blockIdx.x * 256 + threadIdx.x;
        if (i < e) {
            int d = dst[i];
            int pos = atomicAdd(&g_cursor[d], 1);
            g_col[pos] = src[i];
        }
        return;
    }
    int rowbase = (blockIdx.x - SCATTER_BLOCKS) * 64;
    gemm_tile(x, W, rowbase, n, Wsh, Xsh, threadIdx.x);
}

// Standalone GEMM for rounds 1..3
__global__ __launch_bounds__(256) void k_gemm(const float* __restrict__ x,
                                              const float* __restrict__ W, int n) {
    __shared__ float Wsh[DD * DD];
    __shared__ float Xsh[DD * DD];
    gemm_tile(x, W, blockIdx.x * 64, n, Wsh, Xsh, threadIdx.x);
}

// ---- TMA agg: warp per node; up to 16 neighbor rows per chunk fetched by
// the TMA engine into smem (each lane issues its own row), one mbarrier wait
// per chunk, then conflict-free smem reduction. fp32 accumulate, LN, store.
__global__ __launch_bounds__(256) void k_agg_ln_tma(const __grid_constant__ CUtensorMap tmap,
                                                    const float* __restrict__ b,
                                                    const float* __restrict__ gamma,
                                                    const float* __restrict__ beta,
                                                    float* __restrict__ out, int n) {
    __shared__ alignas(128) unsigned char sbuf[8][16 * 128];   // 16KB
    __shared__ alignas(8)  unsigned long long smbar[8];

    int wib  = threadIdx.x >> 5;
    int lane = threadIdx.x & 31;
    int v    = blockIdx.x * 8 + wib;

    unsigned mbar = smem_u32(&smbar[wib]);
    if (lane == 0) MBAR_INIT(mbar);
    __syncthreads();
    if (v >= n) return;

    float dv = g_dis[v];
    int rp0 = g_rowptr[v];
    int rp1 = g_rowptr[v + 1];

    unsigned su = g_h[(size_t)v * 32 + lane];
    float2 acc = __half22float2(*reinterpret_cast<__half2*>(&su));   // self-loop

    unsigned wbu = smem_u32(&sbuf[wib][0]);
    const unsigned* s32 = (const unsigned*)&sbuf[wib][0];
    unsigned phase = 0;

    for (int base = rp0; base < rp1; base += 16) {
        int cnt = min(16, rp1 - base);                 // warp-uniform
        int u = (lane < cnt) ? g_col[base + lane] : 0;
        if (lane == 0) MBAR_EXPECT(mbar, (unsigned)(cnt * 128));
        if (lane < cnt) TMA_ROW(wbu + (unsigned)lane * 128u, &tmap, u, mbar);
        MBAR_WAIT(mbar, phase);
        phase ^= 1u;
        for (int k = 0; k < cnt; k++) {
            unsigned m = s32[k * 32 + lane];
            float2 f = __half22float2(*reinterpret_cast<__half2*>(&m));
            acc.x += f.x;
            acc.y += f.y;
        }
        __syncwarp();
    }
    if (lane == 0) MBAR_INVAL(mbar);

    float2 bb = ((const float2*)b)[lane];
    float a0 = acc.x * dv + bb.x;
    float a1 = acc.y * dv + bb.y;

    float s  = a0 + a1;
    float ss = a0 * a0 + a1 * a1;
    #pragma unroll
    for (int o = 16; o > 0; o >>= 1) {
        s  += __shfl_xor_sync(0xffffffffu, s, o);
        ss += __shfl_xor_sync(0xffffffffu, ss, o);
    }
    float mu  = s * (1.f / 64.f);
    float var = ss * (1.f / 64.f) - mu * mu;
    float inv = rsqrtf(var + 1e-5f);

    float2 gm = ((const float2*)gamma)[lane];
    float2 bt = ((const float2*)beta)[lane];
    float2 o2;
    o2.x = (a0 - mu) * inv * gm.x + bt.x;
    o2.y = (a1 - mu) * inv * gm.y + bt.y;
    ((float2*)out)[(size_t)v * 32 + lane] = o2;
}

// ---- Fallback agg (R13-proven LDG path, 138us) ----
__global__ __launch_bounds__(256) void k_agg_ln(const float* __restrict__ b,
                                                const float* __restrict__ gamma,
                                                const float* __restrict__ beta,
                                                float* __restrict__ out, int n) {
    int v    = (blockIdx.x * blockDim.x + threadIdx.x) >> 5;
    int lane = threadIdx.x & 31;
    if (v >= n) return;

    const unsigned* gh = g_h;
    float dv = g_dis[v];

    unsigned su = gh[(size_t)v * 32 + lane];
    float2 acc = __half22float2(*reinterpret_cast<__half2*>(&su));

    int rp0 = g_rowptr[v];
    int rp1 = g_rowptr[v + 1];
    for (int base = rp0; base < rp1; base += 32) {
        int j = base + lane;
        int c = (j < rp1) ? g_col[j] : 0;
        int cnt = min(32, rp1 - base);
        int jj = 0;
        for (; jj + 4 <= cnt; jj += 4) {
            int u0 = __shfl_sync(0xffffffffu, c, jj + 0);
            int u1 = __shfl_sync(0xffffffffu, c, jj + 1);
            int u2 = __shfl_sync(0xffffffffu, c, jj + 2);
            int u3 = __shfl_sync(0xffffffffu, c, jj + 3);
            unsigned w0 = gh[(size_t)u0 * 32 + lane];
            unsigned w1 = gh[(size_t)u1 * 32 + lane];
            unsigned w2 = gh[(size_t)u2 * 32 + lane];
            unsigned w3 = gh[(size_t)u3 * 32 + lane];
            float2 m0 = __half22float2(*reinterpret_cast<__half2*>(&w0));
            float2 m1 = __half22float2(*reinterpret_cast<__half2*>(&w1));
            float2 m2 = __half22float2(*reinterpret_cast<__half2*>(&w2));
            float2 m3 = __half22float2(*reinterpret_cast<__half2*>(&w3));
            acc.x += (m0.x + m1.x) + (m2.x + m3.x);
            acc.y += (m0.y + m1.y) + (m2.y + m3.y);
        }
        for (; jj < cnt; jj++) {
            int u = __shfl_sync(0xffffffffu, c, jj);
            unsigned wv = gh[(size_t)u * 32 + lane];
            float2 m = __half22float2(*reinterpret_cast<__half2*>(&wv));
            acc.x += m.x;
            acc.y += m.y;
        }
    }

    float2 bb = ((const float2*)b)[lane];
    float a0 = acc.x * dv + bb.x;
    float a1 = acc.y * dv + bb.y;

    float s  = a0 + a1;
    float ss = a0 * a0 + a1 * a1;
    #pragma unroll
    for (int o = 16; o > 0; o >>= 1) {
        s  += __shfl_xor_sync(0xffffffffu, s, o);
        ss += __shfl_xor_sync(0xffffffffu, ss, o);
    }
    float mu  = s * (1.f / 64.f);
    float var = ss * (1.f / 64.f) - mu * mu;
    float inv = rsqrtf(var + 1e-5f);

    float2 gm = ((const float2*)gamma)[lane];
    float2 bt = ((const float2*)beta)[lane];
    float2 o2;
    o2.x = (a0 - mu) * inv * gm.x + bt.x;
    o2.y = (a1 - mu) * inv * gm.y + bt.y;
    ((float2*)out)[(size_t)v * 32 + lane] = o2;
}

// ---------------- launch ----------------

typedef CUresult (*EncodeTiledFn)(CUtensorMap*, CUtensorMapDataType, cuuint32_t, void*,
                                  const cuuint64_t*, const cuuint64_t*,
                                  const cuuint32_t*, const cuuint32_t*,
                                  CUtensorMapInterleave, CUtensorMapSwizzle,
                                  CUtensorMapL2promotion, CUtensorMapFloatOOBfill);

extern "C" void kernel_launch(void* const* d_in, const int* in_sizes, int n_in,
                              void* d_out, int out_size) {
    const float* x     = (const float*)d_in[0];
    const int*   ei    = (const int*)d_in[1];
    const float* W     = (const float*)d_in[2];
    const float* b     = (const float*)d_in[3];
    const float* gamma = (const float*)d_in[4];
    const float* beta  = (const float*)d_in[5];

    int n = in_sizes[0] / DD;      // 100000
    int e = in_sizes[1] / 2;       // 800000
    const int* src = ei;
    const int* dst = ei + e;

    // Build tensormap for g_h as a 2D [n rows x 128 bytes] tensor (host-side,
    // not a stream op; value captured into the graph via __grid_constant__).
    CUtensorMap tmap;
    bool tma_ok = false;
    {
        void* fn = nullptr;
        cudaDriverEntryPointQueryResult qres = cudaDriverEntryPointSymbolNotFound;
        cudaError_t er = cudaGetDriverEntryPoint("cuTensorMapEncodeTiled", &fn,
                                                 cudaEnableDefault, &qres);
        if (er == cudaSuccess && fn != nullptr && qres == cudaDriverEntryPointSuccess) {
            void* gh_ptr = nullptr;
            cudaGetSymbolAddress(&gh_ptr, g_h);
            cuuint64_t gdims[2]  = {128, (cuuint64_t)n};
            cuuint64_t gstr[1]   = {128};
            cuuint32_t boxd[2]   = {128, 1};
            cuuint32_t estr[2]   = {1, 1};
            CUresult r = ((EncodeTiledFn)fn)(&tmap, CU_TENSOR_MAP_DATA_TYPE_UINT8, 2,
                                             gh_ptr, gdims, gstr, boxd, estr,
                                             CU_TENSOR_MAP_INTERLEAVE_NONE,
                                             CU_TENSOR_MAP_SWIZZLE_NONE,
                                             CU_TENSOR_MAP_L2_PROMOTION_L2_128B,
                                             CU_TENSOR_MAP_FLOAT_OOB_FILL_NONE);
            tma_ok = (r == CUDA_SUCCESS);
        }
    }

    k_hist<<<(e + 255) / 256, 256>>>(dst, e);
    k_scan<<<1, 1024>>>(n);
    k_scatter_gemm<<<SCATTER_BLOCKS + GEMM_BLOCKS, 256>>>(src, dst, e, x, W, n);

    int agg_blocks = (n + 7) / 8;   // warp per node, 8 warps/block

    const int NUM_ROUNDS = 4;
    for (int r = 0; r < NUM_ROUNDS; r++) {
        if (r > 0)
            k_gemm<<<GEMM_BLOCKS, 256>>>((const float*)g_x, W, n);
        float* xout = (r == NUM_ROUNDS - 1) ? (float*)d_out : g_x;
        if (tma_ok)
            k_agg_ln_tma<<<agg_blocks, 256>>>(tmap, b, gamma, beta, xout, n);
        else
            k_agg_ln<<<agg_blocks, 256>>>(b, gamma, beta, xout, n);
    }
}